// round 1
// baseline (speedup 1.0000x reference)
#include <cuda_runtime.h>

#define Bn 4
#define Cn 256
#define Tn 8
#define STRIPEn 8
#define Hn 128
#define Wn 64
#define ICn 128
#define Sn 64              // Tn*STRIPEn tokens
#define REGION 1024        // (Hn/STRIPEn)*Wn contiguous floats per stripe region
#define EPSf 1e-5f

// Scratch (allocation-free: __device__ globals)
__device__ float d_P [Bn*Sn*Cn];    // pooled tokens, [b][s][c]
__device__ float d_g [Bn*Sn*ICn];
__device__ float d_th[Bn*Sn*ICn];
__device__ float d_ph[Bn*Sn*ICn];
__device__ float d_y [Bn*Sn*ICn];
__device__ float d_val[Bn*Cn*Sn];   // BN-folded broadcast values, [b][c][s]

// ---------------------------------------------------------------------------
// K1: stripe mean pool. One warp per output chunk; each chunk is 1024
// contiguous floats at x + o*1024 with o = (b*C+c)*S + s.
// ---------------------------------------------------------------------------
__global__ void pool_kernel(const float* __restrict__ x) {
    int warp = (blockIdx.x * blockDim.x + threadIdx.x) >> 5;   // 0..65535
    int lane = threadIdx.x & 31;
    const float4* p = (const float4*)(x + (size_t)warp * REGION);
    float sum = 0.f;
#pragma unroll
    for (int i = 0; i < 8; i++) {
        float4 v = p[lane + i * 32];
        sum += (v.x + v.y) + (v.z + v.w);
    }
#pragma unroll
    for (int o = 16; o; o >>= 1) sum += __shfl_down_sync(0xffffffffu, sum, o);
    if (lane == 0) {
        int o   = warp;
        int b   = o / (Cn * Sn);
        int rem = o % (Cn * Sn);
        int c   = rem / Sn;
        int s   = rem % Sn;
        d_P[(b * Sn + s) * Cn + c] = sum * (1.0f / REGION);
    }
}

// ---------------------------------------------------------------------------
// K2: g / theta / phi projections. blockIdx = b*S+s (256 blocks), thread = i.
// P row staged in smem; three dots share the P loads.
// ---------------------------------------------------------------------------
__global__ void proj_kernel(const float* __restrict__ g_w,  const float* __restrict__ g_b,
                            const float* __restrict__ th_w, const float* __restrict__ th_b,
                            const float* __restrict__ ph_w, const float* __restrict__ ph_b) {
    __shared__ float pr[Cn];
    int bs = blockIdx.x;      // b*S + s
    int i  = threadIdx.x;     // 0..127
    pr[i]        = d_P[bs * Cn + i];
    pr[i + 128]  = d_P[bs * Cn + i + 128];
    __syncthreads();
    float ag = 0.f, at = 0.f, ap = 0.f;
    const float* gw = g_w  + i * Cn;
    const float* tw = th_w + i * Cn;
    const float* pw = ph_w + i * Cn;
#pragma unroll 8
    for (int c = 0; c < Cn; c++) {
        float p = pr[c];
        ag = fmaf(p, gw[c], ag);
        at = fmaf(p, tw[c], at);
        ap = fmaf(p, pw[c], ap);
    }
    d_g [bs * ICn + i] = ag + g_b[i];
    d_th[bs * ICn + i] = at + th_b[i];
    d_ph[bs * ICn + i] = ap + ph_b[i];
}

// ---------------------------------------------------------------------------
// K3: 64-token attention per batch. f = th @ ph^T, row softmax, y = attn @ g.
// One block per batch, 256 threads. f (16KB) in smem; th/ph/g hit L1/L2.
// ---------------------------------------------------------------------------
__global__ void attn_kernel() {
    __shared__ float sf[Sn * Sn];    // 16 KB
    int b   = blockIdx.x;
    int tid = threadIdx.x;           // 0..255
    const float* th = d_th + b * Sn * ICn;
    const float* ph = d_ph + b * Sn * ICn;
    const float* g  = d_g  + b * Sn * ICn;

    // f[s][r] = dot(th[s], ph[r])
    for (int e = tid; e < Sn * Sn; e += 256) {
        int s = e >> 6, r = e & 63;
        const float* a  = th + s * ICn;
        const float* bb = ph + r * ICn;
        float acc = 0.f;
#pragma unroll 8
        for (int i = 0; i < ICn; i++) acc = fmaf(a[i], bb[i], acc);
        sf[e] = acc;
    }
    __syncthreads();

    // softmax per row: 8 warps, each handles 8 rows of 64
    int warp = tid >> 5, lane = tid & 31;
    for (int s = warp; s < Sn; s += 8) {
        float* row = sf + s * Sn;
        float v0 = row[lane], v1 = row[lane + 32];
        float m = fmaxf(v0, v1);
#pragma unroll
        for (int o = 16; o; o >>= 1) m = fmaxf(m, __shfl_xor_sync(0xffffffffu, m, o));
        float e0 = __expf(v0 - m), e1 = __expf(v1 - m);
        float sum = e0 + e1;
#pragma unroll
        for (int o = 16; o; o >>= 1) sum += __shfl_xor_sync(0xffffffffu, sum, o);
        float inv = 1.0f / sum;
        row[lane]      = e0 * inv;
        row[lane + 32] = e1 * inv;
    }
    __syncthreads();

    // y[s][i] = sum_r attn[s][r] * g[r][i]
    float* y = d_y + b * Sn * ICn;
    for (int e = tid; e < Sn * ICn; e += 256) {
        int s = e >> 7, i = e & 127;
        const float* arow = sf + s * Sn;
        float acc = 0.f;
#pragma unroll 8
        for (int r = 0; r < Sn; r++) acc = fmaf(arow[r], g[r * ICn + i], acc);
        y[e] = acc;
    }
}

// ---------------------------------------------------------------------------
// K4: output projection + folded BatchNorm (eval mode).
// blockIdx = b*C + c (1024 blocks), thread = s (64). W row staged in smem.
// ---------------------------------------------------------------------------
__global__ void wproj_kernel(const float* __restrict__ W_w,   const float* __restrict__ W_b,
                             const float* __restrict__ gamma, const float* __restrict__ beta,
                             const float* __restrict__ mean,  const float* __restrict__ var) {
    __shared__ float wrow[ICn];
    int bc = blockIdx.x;
    int b  = bc / Cn, c = bc % Cn;
    int s  = threadIdx.x;            // 0..63
    wrow[s]      = W_w[c * ICn + s];
    wrow[s + 64] = W_w[c * ICn + s + 64];
    __syncthreads();
    const float* y = d_y + (b * Sn + s) * ICn;
    float acc = 0.f;
#pragma unroll 8
    for (int i = 0; i < ICn; i++) acc = fmaf(y[i], wrow[i], acc);
    float inv = gamma[c] * rsqrtf(var[c] + EPSf);
    d_val[bc * Sn + s] = (acc + W_b[c] - mean[c]) * inv + beta[c];
}

// ---------------------------------------------------------------------------
// K5: broadcast + residual. Each 1024-float chunk o gets + d_val[o].
// Pure float4 stream: read x, write z.
// ---------------------------------------------------------------------------
__global__ void residual_kernel(const float* __restrict__ x, float* __restrict__ z) {
    int idx = blockIdx.x * blockDim.x + threadIdx.x;   // float4 index, 16.78M total
    float v = d_val[idx >> 8];                         // 256 float4 per chunk
    float4 a = ((const float4*)x)[idx];
    a.x += v; a.y += v; a.z += v; a.w += v;
    ((float4*)z)[idx] = a;
}

// ---------------------------------------------------------------------------
extern "C" void kernel_launch(void* const* d_in, const int* in_sizes, int n_in,
                              void* d_out, int out_size) {
    const float* x      = (const float*)d_in[0];
    const float* g_w    = (const float*)d_in[1];
    const float* g_b    = (const float*)d_in[2];
    const float* th_w   = (const float*)d_in[3];
    const float* th_b   = (const float*)d_in[4];
    const float* ph_w   = (const float*)d_in[5];
    const float* ph_b   = (const float*)d_in[6];
    const float* W_w    = (const float*)d_in[7];
    const float* W_b    = (const float*)d_in[8];
    const float* gamma  = (const float*)d_in[9];
    const float* beta   = (const float*)d_in[10];
    const float* mean   = (const float*)d_in[11];
    const float* var    = (const float*)d_in[12];
    float* z = (float*)d_out;

    // K1: 65536 warps, 8 per block
    pool_kernel<<<8192, 256>>>(x);
    // K2: one block per token
    proj_kernel<<<Bn * Sn, 128>>>(g_w, g_b, th_w, th_b, ph_w, ph_b);
    // K3: one block per batch
    attn_kernel<<<Bn, 256>>>();
    // K4: one block per (b, c)
    wproj_kernel<<<Bn * Cn, 64>>>(W_w, W_b, gamma, beta, mean, var);
    // K5: 16.78M float4
    residual_kernel<<<(Bn * Cn * Tn * Hn * Wn / 4) / 256, 256>>>(x, z);
}

// round 2
// speedup vs baseline: 3.2800x; 3.2800x over previous
#include <cuda_runtime.h>

#define Bn 4
#define Cn 256
#define Tn 8
#define STRIPEn 8
#define Hn 128
#define Wn 64
#define ICn 128
#define Sn 64              // Tn*STRIPEn tokens per batch
#define NTOK (Bn*Sn)       // 256 flat tokens
#define REGION 1024        // contiguous floats per stripe region
#define EPSf 1e-5f

// Scratch (allocation-free: __device__ globals)
__device__ float d_P   [NTOK*Cn];      // pooled tokens, [tok][c]
__device__ float d_g   [NTOK*ICn];
__device__ float d_th  [NTOK*ICn];
__device__ float d_ph  [NTOK*ICn];
__device__ float d_attn[Bn*Sn*Sn];     // softmax(theta phi^T), [b][s][r]
__device__ float d_y   [NTOK*ICn];
__device__ float d_val [Bn*Cn*Sn];     // BN-folded broadcast values, [b][c][s]

// ---------------------------------------------------------------------------
// K1: stripe mean pool. One warp per 1024-float contiguous region.
// region o = (b*C+c)*S + s  ->  P[(b*S+s)*C + c]
// ---------------------------------------------------------------------------
__global__ void pool_kernel(const float* __restrict__ x) {
    int warp = (blockIdx.x * blockDim.x + threadIdx.x) >> 5;   // 0..65535
    int lane = threadIdx.x & 31;
    const float4* p = (const float4*)(x + (size_t)warp * REGION);
    float sum = 0.f;
#pragma unroll
    for (int i = 0; i < 8; i++) {
        float4 v = p[lane + i * 32];
        sum += (v.x + v.y) + (v.z + v.w);
    }
#pragma unroll
    for (int o = 16; o; o >>= 1) sum += __shfl_down_sync(0xffffffffu, sum, o);
    if (lane == 0) {
        int b   = warp / (Cn * Sn);
        int rem = warp % (Cn * Sn);
        int c   = rem / Sn;
        int s   = rem % Sn;
        d_P[(b * Sn + s) * Cn + c] = sum * (1.0f / REGION);
    }
}

// ---------------------------------------------------------------------------
// K2: g/theta/phi projections as one tiled GEMM.
// O[tok][o] = sum_c P[tok][c] * W[o][c] + bias[o], o in [0,384)
// grid (8 token-tiles, 12 out-tiles), 32x32 tiles, k-tile 32, 256 threads.
// ---------------------------------------------------------------------------
__global__ void proj_kernel(const float* __restrict__ g_w,  const float* __restrict__ g_b,
                            const float* __restrict__ th_w, const float* __restrict__ th_b,
                            const float* __restrict__ ph_w, const float* __restrict__ ph_b) {
    __shared__ float As[32][33];   // P tile  [token][k]
    __shared__ float Bs[32][33];   // W tile  [out][k]
    int t0 = blockIdx.x * 32;            // token tile base
    int oT = blockIdx.y;                 // 0..11
    int mat  = oT >> 2;                  // 0:g 1:th 2:ph
    int row0 = (oT & 3) * 32;            // row within the 128-row matrix
    const float* wsrc = (mat == 0) ? g_w : (mat == 1) ? th_w : ph_w;
    const float* bsrc = (mat == 0) ? g_b : (mat == 1) ? th_b : ph_b;
    float*       osrc = (mat == 0) ? d_g : (mat == 1) ? d_th : d_ph;

    int tid = threadIdx.x;
    int tx = tid & 15, ty = tid >> 4;    // 16x16 thread grid, 2x2 microtile
    float acc[2][2] = {{0.f,0.f},{0.f,0.f}};

    for (int k0 = 0; k0 < Cn; k0 += 32) {
        // load tiles (coalesced, 4 elems each)
#pragma unroll
        for (int l = 0; l < 4; l++) {
            int idx = tid + l * 256;     // 0..1023
            int r = idx >> 5, k = idx & 31;
            As[r][k] = d_P[(t0 + r) * Cn + k0 + k];
            Bs[r][k] = wsrc[(row0 + r) * Cn + k0 + k];
        }
        __syncthreads();
#pragma unroll
        for (int k = 0; k < 32; k++) {
            float a0 = As[ty * 2][k],     a1 = As[ty * 2 + 1][k];
            float b0 = Bs[tx * 2][k],     b1 = Bs[tx * 2 + 1][k];
            acc[0][0] = fmaf(a0, b0, acc[0][0]);
            acc[0][1] = fmaf(a0, b1, acc[0][1]);
            acc[1][0] = fmaf(a1, b0, acc[1][0]);
            acc[1][1] = fmaf(a1, b1, acc[1][1]);
        }
        __syncthreads();
    }
#pragma unroll
    for (int di = 0; di < 2; di++) {
#pragma unroll
        for (int dj = 0; dj < 2; dj++) {
            int tok = t0 + ty * 2 + di;
            int i   = row0 + tx * 2 + dj;        // row within matrix (0..127)
            osrc[tok * ICn + i] = acc[di][dj] + bsrc[i];
        }
    }
}

// ---------------------------------------------------------------------------
// K3a: f = theta @ phi^T + row softmax -> d_attn.
// grid = 4 batches x 4 row-groups (16 s-rows each), 256 threads.
// ---------------------------------------------------------------------------
__global__ void attn_f_kernel() {
    __shared__ float ph_s[Sn * 129];     // padded [r][i], 33KB
    __shared__ float th_s[16 * ICn];     // [srow][i], 8KB
    __shared__ float fs[16 * Sn];        // [srow][r], 4KB
    int b  = blockIdx.x >> 2;
    int s0 = (blockIdx.x & 3) * 16;
    int tid = threadIdx.x;
    const float* ph = d_ph + b * Sn * ICn;
    const float* th = d_th + (b * Sn + s0) * ICn;

    for (int idx = tid; idx < Sn * ICn; idx += 256) {
        int r = idx >> 7, i = idx & 127;
        ph_s[r * 129 + i] = ph[idx];
    }
    for (int idx = tid; idx < 16 * ICn; idx += 256)
        th_s[idx] = th[idx];
    __syncthreads();

    // fs[srow][r]: 1024 outputs, 4 per thread
    int r = tid & 63;
    int sr0 = tid >> 6;                  // 0..3
#pragma unroll
    for (int pass = 0; pass < 4; pass++) {
        int srow = pass * 4 + sr0;
        const float* a = th_s + srow * ICn;
        const float* p = ph_s + r * 129;
        float acc = 0.f;
#pragma unroll 16
        for (int i = 0; i < ICn; i++) acc = fmaf(a[i], p[i], acc);
        fs[srow * Sn + r] = acc;
    }
    __syncthreads();

    // softmax per row (64 wide): 8 warps x 2 rows each
    int warp = tid >> 5, lane = tid & 31;
    float* out = d_attn + b * Sn * Sn;
#pragma unroll
    for (int rr = 0; rr < 2; rr++) {
        int srow = warp * 2 + rr;
        float* row = fs + srow * Sn;
        float v0 = row[lane], v1 = row[lane + 32];
        float m = fmaxf(v0, v1);
#pragma unroll
        for (int o = 16; o; o >>= 1) m = fmaxf(m, __shfl_xor_sync(0xffffffffu, m, o));
        float e0 = __expf(v0 - m), e1 = __expf(v1 - m);
        float sum = e0 + e1;
#pragma unroll
        for (int o = 16; o; o >>= 1) sum += __shfl_xor_sync(0xffffffffu, sum, o);
        float inv = 1.0f / sum;
        out[(s0 + srow) * Sn + lane]      = e0 * inv;
        out[(s0 + srow) * Sn + lane + 32] = e1 * inv;
    }
}

// ---------------------------------------------------------------------------
// K3b: y = attn @ g.  grid = 4 batches x 4 row-groups (16 s each), 256 thr.
// ---------------------------------------------------------------------------
__global__ void attn_y_kernel() {
    __shared__ float g_s[Sn * ICn];      // 32KB, stride-1 reads -> no pad needed
    __shared__ float a_s[16 * Sn];       // 4KB
    int b  = blockIdx.x >> 2;
    int s0 = (blockIdx.x & 3) * 16;
    int tid = threadIdx.x;
    const float* g = d_g + b * Sn * ICn;
    const float* at = d_attn + (b * Sn + s0) * Sn;

    for (int idx = tid; idx < Sn * ICn; idx += 256) g_s[idx] = g[idx];
    for (int idx = tid; idx < 16 * Sn; idx += 256)  a_s[idx] = at[idx];
    __syncthreads();

    float* y = d_y + (b * Sn + s0) * ICn;
    int i = tid & 127;
    int sr0 = tid >> 7;                  // 0..1
#pragma unroll
    for (int pass = 0; pass < 8; pass++) {
        int srow = pass * 2 + sr0;
        const float* arow = a_s + srow * Sn;
        float acc = 0.f;
#pragma unroll 16
        for (int r = 0; r < Sn; r++) acc = fmaf(arow[r], g_s[r * ICn + i], acc);
        y[srow * ICn + i] = acc;
    }
}

// ---------------------------------------------------------------------------
// K4: output projection + folded BatchNorm.
// grid = 4 b x 16 c-chunks (16 c each) = 64 blocks, 256 threads.
// y staged transposed (padded) so val[c][s] dots are conflict-free & coalesced.
// ---------------------------------------------------------------------------
__global__ void wproj_kernel(const float* __restrict__ W_w,   const float* __restrict__ W_b,
                             const float* __restrict__ gamma, const float* __restrict__ beta,
                             const float* __restrict__ mean,  const float* __restrict__ var) {
    __shared__ float y_t[ICn * 65];      // [i][s] padded, 33.3KB
    __shared__ float Ws[16 * ICn];       // [c_local][i], 8KB
    int b  = blockIdx.x >> 4;
    int c0 = (blockIdx.x & 15) * 16;
    int tid = threadIdx.x;
    const float* y = d_y + b * Sn * ICn;

    for (int idx = tid; idx < Sn * ICn; idx += 256) {
        int s = idx >> 7, i = idx & 127;
        y_t[i * 65 + s] = y[idx];
    }
    for (int idx = tid; idx < 16 * ICn; idx += 256)
        Ws[idx] = W_w[c0 * ICn + idx];
    __syncthreads();

    int s = tid & 63;
    int cl0 = tid >> 6;                  // 0..3
#pragma unroll
    for (int pass = 0; pass < 4; pass++) {
        int cl = pass * 4 + cl0;
        int c  = c0 + cl;
        const float* w = Ws + cl * ICn;
        float acc = 0.f;
#pragma unroll 16
        for (int i = 0; i < ICn; i++) acc = fmaf(w[i], y_t[i * 65 + s], acc);
        float inv = gamma[c] * rsqrtf(var[c] + EPSf);
        d_val[(b * Cn + c) * Sn + s] = (acc + W_b[c] - mean[c]) * inv + beta[c];
    }
}

// ---------------------------------------------------------------------------
// K5: broadcast + residual. Pure float4 stream.
// ---------------------------------------------------------------------------
__global__ void residual_kernel(const float* __restrict__ x, float* __restrict__ z) {
    int idx = blockIdx.x * blockDim.x + threadIdx.x;   // float4 index
    float v = d_val[idx >> 8];                         // 256 float4 per region
    float4 a = ((const float4*)x)[idx];
    a.x += v; a.y += v; a.z += v; a.w += v;
    ((float4*)z)[idx] = a;
}

// ---------------------------------------------------------------------------
extern "C" void kernel_launch(void* const* d_in, const int* in_sizes, int n_in,
                              void* d_out, int out_size) {
    const float* x      = (const float*)d_in[0];
    const float* g_w    = (const float*)d_in[1];
    const float* g_b    = (const float*)d_in[2];
    const float* th_w   = (const float*)d_in[3];
    const float* th_b   = (const float*)d_in[4];
    const float* ph_w   = (const float*)d_in[5];
    const float* ph_b   = (const float*)d_in[6];
    const float* W_w    = (const float*)d_in[7];
    const float* W_b    = (const float*)d_in[8];
    const float* gamma  = (const float*)d_in[9];
    const float* beta   = (const float*)d_in[10];
    const float* mean   = (const float*)d_in[11];
    const float* var    = (const float*)d_in[12];
    float* z = (float*)d_out;

    pool_kernel<<<8192, 256>>>(x);
    dim3 pg(NTOK / 32, 12);
    proj_kernel<<<pg, 256>>>(g_w, g_b, th_w, th_b, ph_w, ph_b);
    attn_f_kernel<<<16, 256>>>();
    attn_y_kernel<<<16, 256>>>();
    wproj_kernel<<<64, 256>>>(W_w, W_b, gamma, beta, mean, var);
    residual_kernel<<<(Bn * Cn * Tn * Hn * Wn / 4) / 256, 256>>>(x, z);
}